// round 4
// baseline (speedup 1.0000x reference)
#include <cuda_runtime.h>
#include <math.h>

#define D    256
#define G3   768
#define MAXR 4096
#define NB   96      // mega-kernel grid size (must be <= #SMs for the grid barrier)

// ---------------- device scratch (static globals; no allocation) ----------------
__device__ float g_sub[D];
__device__ float g_gi0[G3];
__device__ float g_gh0[G3];
__device__ float g_gi[G3];
__device__ float g_gh[(size_t)MAXR * G3];
__device__ float g_rj[(size_t)MAXR * D];
__device__ float g_obj[(size_t)MAXR * D];
__device__ unsigned g_bcnt;   // zero-init; self-resetting
__device__ unsigned g_bgen;   // monotonically increasing across replays

// ---------------- helpers -------------------------------------------------------
__device__ __forceinline__ float dot8(float4 a0, float4 a1, float4 x0, float4 x1) {
    return a0.x*x0.x + a0.y*x0.y + a0.z*x0.z + a0.w*x0.w
         + a1.x*x1.x + a1.y*x1.y + a1.z*x1.z + a1.w*x1.w;
}
__device__ __forceinline__ float wred(float v) {
#pragma unroll
    for (int o = 16; o; o >>= 1) v += __shfl_xor_sync(0xffffffffu, v, o);
    return v;
}
__device__ __forceinline__ float sigf(float x) { return 1.f / (1.f + __expf(-x)); }

__device__ __forceinline__ unsigned long long pack2(float x, float y) {
    unsigned long long r;
    asm("mov.b64 %0, {%1, %2};" : "=l"(r) : "f"(x), "f"(y));
    return r;
}
__device__ __forceinline__ void unpack2(unsigned long long v, float& x, float& y) {
    asm("mov.b64 {%0, %1}, %2;" : "=f"(x), "=f"(y) : "l"(v));
}
__device__ __forceinline__ void ffma2(unsigned long long& d, unsigned long long a,
                                      unsigned long long b) {
    asm("fma.rn.f32x2 %0, %1, %2, %0;" : "+l"(d) : "l"(a), "l"(b));
}

// self-resetting grid barrier (all NB blocks guaranteed co-resident: NB < #SMs)
__device__ __forceinline__ void grid_bar() {
    __syncthreads();
    if (threadIdx.x == 0) {
        __threadfence();
        unsigned my = *(volatile unsigned*)&g_bgen;
        if (atomicAdd(&g_bcnt, 1u) == (unsigned)(NB - 1)) {
            *(volatile unsigned*)&g_bcnt = 0;
            __threadfence();
            atomicAdd(&g_bgen, 1u);
        } else {
            while (*(volatile unsigned*)&g_bgen == my) { }
            __threadfence();
        }
    }
    __syncthreads();
}

// ---------------- in-kernel NT GEMM tile (f32x2 packed FMA) ---------------------
// C[m0..m0+63, n0..n0+BN) += act(A[m,:].B[n,:] + bias[n]) ; K=256, M ragged.
template <int BN, int TN, bool TANH>
__device__ void tile_gemm(const float* __restrict__ A, const float* __restrict__ B,
                          const float* __restrict__ bias, float* __restrict__ C,
                          int M, int ldc, int K, int m0, int n0,
                          float (*As)[68], float (*Bs)[132]) {
    const int BM = 64, BK = 32, TM = 4;
    int tid = threadIdx.x;
    unsigned long long acc[TM][TN / 2];
#pragma unroll
    for (int i = 0; i < TM; i++)
#pragma unroll
        for (int j = 0; j < TN / 2; j++) acc[i][j] = 0ull;
    int tm = (tid & 15) * TM;
    int tn = (tid >> 4) * TN;

    for (int k0 = 0; k0 < K; k0 += BK) {
#pragma unroll
        for (int i = 0; i < (BM * BK) / (256 * 4); i++) {
            int idx = tid + i * 256;
            int row = idx >> 3, c4 = idx & 7;
            float4 v = make_float4(0.f, 0.f, 0.f, 0.f);
            if (m0 + row < M) v = *(const float4*)&A[(size_t)(m0 + row) * K + k0 + c4 * 4];
            As[c4 * 4 + 0][row] = v.x; As[c4 * 4 + 1][row] = v.y;
            As[c4 * 4 + 2][row] = v.z; As[c4 * 4 + 3][row] = v.w;
        }
#pragma unroll
        for (int i = 0; i < (BN * BK) / (256 * 4); i++) {
            int idx = tid + i * 256;
            int row = idx >> 3, c4 = idx & 7;
            float4 v = *(const float4*)&B[(size_t)(n0 + row) * K + k0 + c4 * 4];
            Bs[c4 * 4 + 0][row] = v.x; Bs[c4 * 4 + 1][row] = v.y;
            Bs[c4 * 4 + 2][row] = v.z; Bs[c4 * 4 + 3][row] = v.w;
        }
        __syncthreads();
#pragma unroll
        for (int k = 0; k < BK; k++) {
            float4 av = *(const float4*)&As[k][tm];
            unsigned long long pa[TM];
            pa[0] = pack2(av.x, av.x); pa[1] = pack2(av.y, av.y);
            pa[2] = pack2(av.z, av.z); pa[3] = pack2(av.w, av.w);
            unsigned long long pb[TN / 2];
#pragma unroll
            for (int j4 = 0; j4 < TN / 4; j4++) {
                float4 bv = *(const float4*)&Bs[k][tn + j4 * 4];
                pb[j4 * 2 + 0] = pack2(bv.x, bv.y);
                pb[j4 * 2 + 1] = pack2(bv.z, bv.w);
            }
#pragma unroll
            for (int i = 0; i < TM; i++)
#pragma unroll
                for (int j = 0; j < TN / 2; j++) ffma2(acc[i][j], pa[i], pb[j]);
        }
        __syncthreads();
    }
#pragma unroll
    for (int i = 0; i < TM; i++) {
        int m = m0 + tm + i;
        if (m < M) {
#pragma unroll
            for (int j = 0; j < TN / 2; j++) {
                float vx, vy; unpack2(acc[i][j], vx, vy);
                int n = n0 + tn + j * 2;
                if (bias) { vx += bias[n]; vy += bias[n + 1]; }
                if (TANH) { vx = tanhf(vx); vy = tanhf(vy); }
                C[(size_t)m * ldc + n]     = vx;
                C[(size_t)m * ldc + n + 1] = vy;
            }
        }
    }
}

// ---------------- mega compute kernel (phases separated by grid barrier) --------
__global__ void __launch_bounds__(256)
mega_kernel(const float* __restrict__ sub_W, const float* __restrict__ W_ih,
            const float* __restrict__ W_hh,  const float* __restrict__ mask,
            const float* __restrict__ enc,   const float* __restrict__ sub_b,
            const float* __restrict__ b_ih,  const float* __restrict__ b_hh,
            const float* __restrict__ relT,  const float* __restrict__ obj_W,
            const float* __restrict__ obj_b, float* __restrict__ out,
            const int* __restrict__ seed_p,  int R) {
    __shared__ float sAs[32][68];
    __shared__ float sBs[32][132];
    int t = threadIdx.x, w = t >> 5, l = t & 31, b = blockIdx.x;

    // ---- p0: sub = tanh(sub_W@mask+sub_b) (+ seed row of out) ; gi0 = W_ih@enc+b_ih
#pragma unroll
    for (int it = 0; it < 2; it++) {
        int j = it * (NB * 8) + b * 8 + w;
        if (j < 1024) {
            const float4 *Wr, *x; float bias;
            if (j < 256) { Wr = (const float4*)(sub_W + (size_t)j * D); x = (const float4*)mask; bias = sub_b[j]; }
            else { Wr = (const float4*)(W_ih + (size_t)(j - 256) * D); x = (const float4*)enc; bias = b_ih[j - 256]; }
            float acc = wred(dot8(Wr[l], Wr[l + 32], __ldg(x + l), __ldg(x + l + 32)));
            if (l == 0) {
                acc += bias;
                if (j < 256) { float tt = tanhf(acc); g_sub[j] = tt; out[(size_t)seed_p[0] * D + j] = tt; }
                else g_gi0[j - 256] = acc;
            }
        }
    }
    grid_bar();

    // ---- p1: gh0 = W_hh @ sub + b_hh
    {
        int j = b * 8 + w;
        const float4* Wr = (const float4*)(W_hh + (size_t)j * D);
        const float4* x  = (const float4*)g_sub;
        float acc = wred(dot8(Wr[l], Wr[l + 32], x[l], x[l + 32]));
        if (l == 0) g_gh0[j] = acc + b_hh[j];
    }
    grid_bar();

    // ---- p2: r0 (per-block in smem) ; gi = W_ih @ r0 + b_ih
    {
        float* r0s = &sBs[0][0];
        float r = sigf(g_gi0[t] + g_gh0[t]);
        float z = sigf(g_gi0[D + t] + g_gh0[D + t]);
        float n = tanhf(g_gi0[2 * D + t] + r * g_gh0[2 * D + t]);
        r0s[t] = (1.f - z) * n + z * g_sub[t];
        __syncthreads();
        int j = b * 8 + w;
        const float4* Wr = (const float4*)(W_ih + (size_t)j * D);
        const float4* x  = (const float4*)r0s;
        float acc = wred(dot8(Wr[l], Wr[l + 32], x[l], x[l + 32]));
        if (l == 0) g_gi[j] = acc + b_ih[j];
    }
    grid_bar();

    // ---- p3: gh = relT @ W_hh^T  (96 tiles of 64x128 over [R,768])
    tile_gemm<128, 8, false>(relT, W_hh, nullptr, g_gh, R, G3, D,
                             (b % 16) * 64, (b / 16) * 128, sAs, sBs);
    grid_bar();

    // ---- p4: rj[r,d] from gh row + gi + b_hh + rel_emb
    {
        float gi_r = g_gi[t], gi_z = g_gi[D + t], gi_n = g_gi[2 * D + t];
        float bh_r = b_hh[t], bh_z = b_hh[D + t], bh_n = b_hh[2 * D + t];
        for (int r = b; r < R; r += NB) {
            const float* gh = g_gh + (size_t)r * G3;
            float rr = sigf(gi_r + gh[t] + bh_r);
            float z  = sigf(gi_z + gh[D + t] + bh_z);
            float n  = tanhf(gi_n + rr * (gh[2 * D + t] + bh_n));
            g_rj[(size_t)r * D + t] = (1.f - z) * n + z * relT[(size_t)r * D + t];
        }
    }
    grid_bar();

    // ---- p5: obj = tanh(rj @ obj_W^T + obj_b)  (64 tiles of 64x64 over [R,256])
    if (b < 64)
        tile_gemm<64, 4, true>(g_rj, obj_W, obj_b, g_obj, R, D, D,
                               (b % 16) * 64, (b / 16) * 64, sAs, sBs);
}

// ---------------- scatter A: state==1: out[tail] = ent[origin] ------------------
__global__ void scatter_ent(const int* __restrict__ tail, const int* __restrict__ st,
                            const int* __restrict__ org,  const float* __restrict__ entT,
                            float* __restrict__ out, int E) {
#if __CUDA_ARCH__ >= 900
    cudaTriggerProgrammaticLaunchCompletion();   // let the mega kernel co-reside
#endif
    int l   = threadIdx.x & 31;
    int wid = (blockIdx.x * blockDim.x + threadIdx.x) >> 5;
    int nw  = (gridDim.x * blockDim.x) >> 5;
    for (int e = wid; e < E; e += nw) {
        if (st[e] == 1) {
            const float4* s = (const float4*)(entT + (size_t)org[e] * D);
            float4* d = (float4*)(out + (size_t)tail[e] * D);
            float4 v0 = __ldcs(s + l), v1 = __ldcs(s + l + 32);
            __stcs(d + l, v0); __stcs(d + l + 32, v1);
        }
    }
}

// ---------------- scatter B: state!=1: out[tail] = obj_table[rel] ---------------
__global__ void scatter_obj(const int* __restrict__ rel, const int* __restrict__ tail,
                            const int* __restrict__ st, float* __restrict__ out, int E) {
#if __CUDA_ARCH__ >= 900
    cudaGridDependencySynchronize();             // wait only on mega completion
#endif
    int l   = threadIdx.x & 31;
    int wid = (blockIdx.x * blockDim.x + threadIdx.x) >> 5;
    int nw  = (gridDim.x * blockDim.x) >> 5;
    for (int e = wid; e < E; e += nw) {
        if (st[e] != 1) {
            const float4* s = (const float4*)(g_obj + (size_t)rel[e] * D);
            float4* d = (float4*)(out + (size_t)tail[e] * D);
            float4 v0 = __ldg(s + l), v1 = __ldg(s + l + 32);
            __stcs(d + l, v0); __stcs(d + l + 32, v1);
        }
    }
}

// --------------------------------- launcher -------------------------------------
static void launch_pss(void* fn, dim3 g, dim3 blk, void** args) {
    cudaLaunchConfig_t cfg = {};
    cfg.gridDim = g; cfg.blockDim = blk; cfg.dynamicSmemBytes = 0; cfg.stream = 0;
    cudaLaunchAttribute at[1];
    at[0].id = cudaLaunchAttributeProgrammaticStreamSerialization;
    at[0].val.programmaticStreamSerializationAllowed = 1;
    cfg.attrs = at; cfg.numAttrs = 1;
    if (cudaLaunchKernelExC(&cfg, fn, args) != cudaSuccess)
        cudaLaunchKernel(fn, g, blk, args, 0, 0);   // serialized fallback, still correct
}

extern "C" void kernel_launch(void* const* d_in, const int* in_sizes, int n_in,
                              void* d_out, int out_size) {
    const float* encoder = (const float*)d_in[0];
    const float* mask    = (const float*)d_in[1];
    const float* entT    = (const float*)d_in[2];
    const float* relT    = (const float*)d_in[3];
    const float* W_ih    = (const float*)d_in[4];
    const float* W_hh    = (const float*)d_in[5];
    const float* b_ih    = (const float*)d_in[6];
    const float* b_hh    = (const float*)d_in[7];
    const float* sub_W   = (const float*)d_in[8];
    const float* sub_b   = (const float*)d_in[9];
    const float* obj_W   = (const float*)d_in[10];
    const float* obj_b   = (const float*)d_in[11];
    const int*   rel_ids = (const int*)d_in[12];
    const int*   tail_ids= (const int*)d_in[13];
    const int*   state   = (const int*)d_in[14];
    const int*   origin  = (const int*)d_in[15];
    const int*   seed_p  = (const int*)d_in[16];
    float* out = (float*)d_out;

    int E = in_sizes[12];
    int R = in_sizes[3] / D;
    if (R > MAXR) R = MAXR;

    // 1) entity gather/scatter: independent; triggers PDL at start.
    scatter_ent<<<740, 256>>>(tail_ids, state, origin, entT, out, E);

    // 2) mega compute kernel: launches immediately (PSS), runs concurrently.
    {
        void* args[] = { (void*)&sub_W, (void*)&W_ih, (void*)&W_hh, (void*)&mask,
                         (void*)&encoder, (void*)&sub_b, (void*)&b_ih, (void*)&b_hh,
                         (void*)&relT, (void*)&obj_W, (void*)&obj_b, (void*)&out,
                         (void*)&seed_p, (void*)&R };
        launch_pss((void*)mega_kernel, dim3(NB), dim3(256), args);
    }

    // 3) obj scatter: PSS -> waits only on mega's completion trigger, not scatter_ent.
    {
        int grid = 1184;
        void* args[] = { (void*)&rel_ids, (void*)&tail_ids, (void*)&state,
                         (void*)&out, (void*)&E };
        launch_pss((void*)scatter_obj, dim3(grid), dim3(256), args);
    }
}

// round 6
// speedup vs baseline: 1.2854x; 1.2854x over previous
#include <cuda_runtime.h>
#include <math.h>

#define D    256
#define G3   768
#define MAXR 4096

// ---------------- device scratch (static globals; no allocation) ----------------
__device__ float g_sub[D];
__device__ float g_gi0[G3];
__device__ float g_gh0[G3];
__device__ float g_gi[G3];
__device__ float g_gh[(size_t)MAXR * G3];
__device__ float g_rj[(size_t)MAXR * D];
__device__ float g_obj[(size_t)MAXR * D];
__device__ unsigned g_gh_done;   // gh GEMM completion counter (reset each run)

// ---------------- helpers -------------------------------------------------------
__device__ __forceinline__ float dot8(float4 a0, float4 a1, float4 x0, float4 x1) {
    return a0.x*x0.x + a0.y*x0.y + a0.z*x0.z + a0.w*x0.w
         + a1.x*x1.x + a1.y*x1.y + a1.z*x1.z + a1.w*x1.w;
}
__device__ __forceinline__ float wred(float v) {
#pragma unroll
    for (int o = 16; o; o >>= 1) v += __shfl_xor_sync(0xffffffffu, v, o);
    return v;
}
__device__ __forceinline__ float sigf(float x) { return 1.f / (1.f + __expf(-x)); }

__device__ __forceinline__ unsigned long long pack2(float x, float y) {
    unsigned long long r;
    asm("mov.b64 %0, {%1, %2};" : "=l"(r) : "f"(x), "f"(y));
    return r;
}
__device__ __forceinline__ void unpack2(unsigned long long v, float& x, float& y) {
    asm("mov.b64 {%0, %1}, %2;" : "=f"(x), "=f"(y) : "l"(v));
}
__device__ __forceinline__ void ffma2(unsigned long long& d, unsigned long long a,
                                      unsigned long long b) {
    asm("fma.rn.f32x2 %0, %1, %2, %0;" : "+l"(d) : "l"(a), "l"(b));
}

// ---------------- K1: sub = tanh(sub_W@mask+sub_b) (+seed write) ; gi0 ----------
__global__ void k1_sub_gi0(const float* __restrict__ sub_W, const float* __restrict__ W_ih,
                           const float* __restrict__ mask,  const float* __restrict__ enc,
                           const float* __restrict__ sub_b, const float* __restrict__ b_ih,
                           float* __restrict__ out, const int* __restrict__ seed_p) {
    int w = threadIdx.x >> 5, l = threadIdx.x & 31;
    int j = blockIdx.x * 8 + w;               // 0..1023
    const float4 *Wr, *x; float bias;
    if (j < 256) { Wr = (const float4*)(sub_W + (size_t)j * D); x = (const float4*)mask; bias = sub_b[j]; }
    else         { Wr = (const float4*)(W_ih + (size_t)(j - 256) * D); x = (const float4*)enc; bias = b_ih[j - 256]; }
    float acc = wred(dot8(Wr[l], Wr[l + 32], __ldg(x + l), __ldg(x + l + 32)));
    if (l == 0) {
        acc += bias;
        if (j < 256) { float t = tanhf(acc); g_sub[j] = t; out[(size_t)seed_p[0] * D + j] = t; }
        else g_gi0[j - 256] = acc;
    }
}

// ---------------- K2: gh0 = W_hh @ sub + b_hh -----------------------------------
__global__ void k2_gh0(const float* __restrict__ W_hh, const float* __restrict__ b_hh) {
    int w = threadIdx.x >> 5, l = threadIdx.x & 31;
    int j = blockIdx.x * 8 + w;
    const float4* Wr = (const float4*)(W_hh + (size_t)j * D);
    const float4* x  = (const float4*)g_sub;
    float acc = wred(dot8(Wr[l], Wr[l + 32], x[l], x[l + 32]));
    if (l == 0) g_gh0[j] = acc + b_hh[j];
}

// ---------------- K3: r0 (in-block) then gi = W_ih @ r0 + b_ih ------------------
__global__ void k3_gi(const float* __restrict__ W_ih, const float* __restrict__ b_ih) {
    __shared__ float r0[D];
    int t = threadIdx.x;
    {
        float r = sigf(g_gi0[t] + g_gh0[t]);
        float z = sigf(g_gi0[D + t] + g_gh0[D + t]);
        float n = tanhf(g_gi0[2 * D + t] + r * g_gh0[2 * D + t]);
        r0[t] = (1.f - z) * n + z * g_sub[t];
    }
    __syncthreads();
    int w = t >> 5, l = t & 31;
    int j = blockIdx.x * 8 + w;
    const float4* Wr = (const float4*)(W_ih + (size_t)j * D);
    const float4* x  = (const float4*)r0;
    float acc = wred(dot8(Wr[l], Wr[l + 32], x[l], x[l + 32]));
    if (l == 0) g_gi[j] = acc + b_ih[j];
}

// ---------------- fp32 NT GEMM (f32x2): C = act(A.B^T + bias) -------------------
// TRIG: call PDL trigger at start; DONE: bump g_gh_done at end.
template <int BN, int TN, bool TANH, bool TRIG, bool DONE>
__global__ __launch_bounds__(256) void gemm_nt(
        const float* __restrict__ A, const float* __restrict__ B,
        const float* __restrict__ bias, float* __restrict__ C,
        int M, int N, int K) {
#if __CUDA_ARCH__ >= 900
    if (TRIG) cudaTriggerProgrammaticLaunchCompletion();
#endif
    const int BM = 64, BK = 32, TM = 4;
    __shared__ float As[BK][BM + 4];
    __shared__ float Bs[BK][BN + 4];
    int tid = threadIdx.x;
    int m0 = blockIdx.x * BM;
    int n0 = blockIdx.y * BN;
    unsigned long long acc[TM][TN / 2];
#pragma unroll
    for (int i = 0; i < TM; i++)
#pragma unroll
        for (int j = 0; j < TN / 2; j++) acc[i][j] = 0ull;
    int tm = (tid & 15) * TM;
    int tn = (tid >> 4) * TN;

    for (int k0 = 0; k0 < K; k0 += BK) {
#pragma unroll
        for (int i = 0; i < (BM * BK) / (256 * 4); i++) {
            int idx = tid + i * 256;
            int row = idx >> 3, c4 = idx & 7;
            float4 v = make_float4(0.f, 0.f, 0.f, 0.f);
            if (m0 + row < M) v = *(const float4*)&A[(size_t)(m0 + row) * K + k0 + c4 * 4];
            As[c4 * 4 + 0][row] = v.x; As[c4 * 4 + 1][row] = v.y;
            As[c4 * 4 + 2][row] = v.z; As[c4 * 4 + 3][row] = v.w;
        }
#pragma unroll
        for (int i = 0; i < (BN * BK) / (256 * 4); i++) {
            int idx = tid + i * 256;
            int row = idx >> 3, c4 = idx & 7;
            float4 v = *(const float4*)&B[(size_t)(n0 + row) * K + k0 + c4 * 4];
            Bs[c4 * 4 + 0][row] = v.x; Bs[c4 * 4 + 1][row] = v.y;
            Bs[c4 * 4 + 2][row] = v.z; Bs[c4 * 4 + 3][row] = v.w;
        }
        __syncthreads();
#pragma unroll
        for (int k = 0; k < BK; k++) {
            float4 av = *(const float4*)&As[k][tm];
            unsigned long long pa[TM];
            pa[0] = pack2(av.x, av.x); pa[1] = pack2(av.y, av.y);
            pa[2] = pack2(av.z, av.z); pa[3] = pack2(av.w, av.w);
            unsigned long long pb[TN / 2];
#pragma unroll
            for (int j4 = 0; j4 < TN / 4; j4++) {
                float4 bv = *(const float4*)&Bs[k][tn + j4 * 4];
                pb[j4 * 2 + 0] = pack2(bv.x, bv.y);
                pb[j4 * 2 + 1] = pack2(bv.z, bv.w);
            }
#pragma unroll
            for (int i = 0; i < TM; i++)
#pragma unroll
                for (int j = 0; j < TN / 2; j++) ffma2(acc[i][j], pa[i], pb[j]);
        }
        __syncthreads();
    }
#pragma unroll
    for (int i = 0; i < TM; i++) {
        int m = m0 + tm + i;
        if (m < M) {
#pragma unroll
            for (int j = 0; j < TN / 2; j++) {
                float vx, vy; unpack2(acc[i][j], vx, vy);
                int n = n0 + tn + j * 2;
                if (bias) { vx += bias[n]; vy += bias[n + 1]; }
                if (TANH) { vx = tanhf(vx); vy = tanhf(vy); }
                C[(size_t)m * N + n]     = vx;
                C[(size_t)m * N + n + 1] = vy;
            }
        }
    }
    if (DONE) {
        __syncthreads();
        if (tid == 0) { __threadfence(); atomicAdd(&g_gh_done, 1u); }
    }
}

// ---------------- per-relation GRU combine: rj_table ----------------------------
__global__ void rj_kernel(const float* __restrict__ rel_table,
                          const float* __restrict__ b_hh, int R, unsigned gh_blocks) {
    // ensure gh GEMM (launched earlier, independent) has fully completed
    if (threadIdx.x == 0) {
        while (*(volatile unsigned*)&g_gh_done < gh_blocks) { }
    }
    __syncthreads();
    __threadfence();
    int r = blockIdx.x, d = threadIdx.x;
    const float* gh = g_gh + (size_t)r * G3;
    float rr = sigf(g_gi[d] + gh[d] + b_hh[d]);
    float z  = sigf(g_gi[D + d] + gh[D + d] + b_hh[D + d]);
    float n  = tanhf(g_gi[2 * D + d] + rr * (gh[2 * D + d] + b_hh[2 * D + d]));
    g_rj[(size_t)r * D + d] = (1.f - z) * n + z * rel_table[(size_t)r * D + d];
}

// ---------------- scatter A: state==1: out[tail] = ent[origin] ------------------
__global__ void __launch_bounds__(256) scatter_ent(
        const int* __restrict__ tail, const int* __restrict__ st,
        const int* __restrict__ org,  const float* __restrict__ entT,
        float* __restrict__ out, int E) {
    // block 0 resets the gh completion counter BEFORE triggering the PDL chain
    if (blockIdx.x == 0 && threadIdx.x == 0) {
        g_gh_done = 0u;
        __threadfence();
    }
#if __CUDA_ARCH__ >= 900
    cudaTriggerProgrammaticLaunchCompletion();   // let gh GEMM + k1 chain co-reside
#endif
    int l   = threadIdx.x & 31;
    int wid = (blockIdx.x * blockDim.x + threadIdx.x) >> 5;
    int nw  = (gridDim.x * blockDim.x) >> 5;
    for (int e0 = wid * 2; e0 < E; e0 += nw * 2) {
        int e1 = e0 + 1;
        int s0 = st[e0];
        int s1 = (e1 < E) ? st[e1] : 0;
        bool d0 = (s0 == 1), d1 = (s1 == 1);
        float4 a0, a1, b0, b1;
        if (d0) { const float4* p = (const float4*)(entT + (size_t)org[e0] * D);
                  a0 = __ldcs(p + l); a1 = __ldcs(p + l + 32); }
        if (d1) { const float4* p = (const float4*)(entT + (size_t)org[e1] * D);
                  b0 = __ldcs(p + l); b1 = __ldcs(p + l + 32); }
        if (d0) { float4* d = (float4*)(out + (size_t)tail[e0] * D);
                  __stcs(d + l, a0); __stcs(d + l + 32, a1); }
        if (d1) { float4* d = (float4*)(out + (size_t)tail[e1] * D);
                  __stcs(d + l, b0); __stcs(d + l + 32, b1); }
    }
}

// ---------------- scatter B: state!=1: out[tail] = obj_table[rel] ---------------
__global__ void __launch_bounds__(256) scatter_obj(
        const int* __restrict__ rel, const int* __restrict__ tail,
        const int* __restrict__ st, float* __restrict__ out, int E) {
    int l   = threadIdx.x & 31;
    int wid = (blockIdx.x * blockDim.x + threadIdx.x) >> 5;
    int nw  = (gridDim.x * blockDim.x) >> 5;
    for (int e = wid; e < E; e += nw) {
        if (st[e] != 1) {
            const float4* s = (const float4*)(g_obj + (size_t)rel[e] * D);
            float4* d = (float4*)(out + (size_t)tail[e] * D);
            float4 v0 = __ldg(s + l), v1 = __ldg(s + l + 32);
            __stcs(d + l, v0); __stcs(d + l + 32, v1);
        }
    }
}

// --------------------------------- launcher -------------------------------------
static void launch_pss(void* fn, dim3 g, dim3 blk, void** args) {
    cudaLaunchConfig_t cfg = {};
    cfg.gridDim = g; cfg.blockDim = blk; cfg.dynamicSmemBytes = 0; cfg.stream = 0;
    cudaLaunchAttribute at[1];
    at[0].id = cudaLaunchAttributeProgrammaticStreamSerialization;
    at[0].val.programmaticStreamSerializationAllowed = 1;
    cfg.attrs = at; cfg.numAttrs = 1;
    if (cudaLaunchKernelExC(&cfg, fn, args) != cudaSuccess)
        cudaLaunchKernel(fn, g, blk, args, 0, 0);   // serialized fallback, still correct
}

extern "C" void kernel_launch(void* const* d_in, const int* in_sizes, int n_in,
                              void* d_out, int out_size) {
    const float* encoder = (const float*)d_in[0];
    const float* mask    = (const float*)d_in[1];
    const float* entT    = (const float*)d_in[2];
    const float* relT    = (const float*)d_in[3];
    const float* W_ih    = (const float*)d_in[4];
    const float* W_hh    = (const float*)d_in[5];
    const float* b_ih    = (const float*)d_in[6];
    const float* b_hh    = (const float*)d_in[7];
    const float* sub_W   = (const float*)d_in[8];
    const float* sub_b   = (const float*)d_in[9];
    const float* obj_W   = (const float*)d_in[10];
    const float* obj_b   = (const float*)d_in[11];
    const int*   rel_ids = (const int*)d_in[12];
    const int*   tail_ids= (const int*)d_in[13];
    const int*   state   = (const int*)d_in[14];
    const int*   origin  = (const int*)d_in[15];
    const int*   seed_p  = (const int*)d_in[16];
    float* out = (float*)d_out;

    int E = in_sizes[12];
    int R = in_sizes[3] / D;
    if (R > MAXR) R = MAXR;

    float *p_gh, *p_rj, *p_obj;
    cudaGetSymbolAddress((void**)&p_gh,  g_gh);
    cudaGetSymbolAddress((void**)&p_rj,  g_rj);
    cudaGetSymbolAddress((void**)&p_obj, g_obj);

    int gx = (R + 63) / 64;
    unsigned gh_blocks = (unsigned)(gx * (G3 / 128));
    const float* nobias = nullptr;
    int M_ = R, N3 = G3, K_ = D, ND = D;

    // 1) entity scatter: independent; resets g_gh_done then triggers PDL at start.
    scatter_ent<<<592, 256>>>(tail_ids, state, origin, entT, out, E);

    // 2) gh GEMM (independent of GEMV chain): PSS -> starts at scatter's trigger;
    //    itself triggers at start so k1 also launches immediately.
    {
        void* args[] = { (void*)&relT, (void*)&W_hh, (void*)&nobias, (void*)&p_gh,
                         (void*)&M_, (void*)&N3, (void*)&K_ };
        launch_pss((void*)gemm_nt<128, 8, false, true, true>,
                   dim3(gx, G3 / 128), dim3(256), args);
    }

    // 3) GEMV chain: k1 starts immediately (PSS); k2/k3 chained normally.
    {
        void* args[] = { (void*)&sub_W, (void*)&W_ih, (void*)&mask, (void*)&encoder,
                         (void*)&sub_b, (void*)&b_ih, (void*)&out, (void*)&seed_p };
        launch_pss((void*)k1_sub_gi0, dim3(128), dim3(256), args);
    }
    k2_gh0<<<96, 256>>>(W_hh, b_hh);
    k3_gi<<<96, 256>>>(W_ih, b_ih);

    // 4) rj: waits k3 via stream, waits gh GEMM via done-counter spin.
    rj_kernel<<<R, 256>>>(relT, b_hh, R, gh_blocks);

    // 5) obj GEMM then obj scatter (overlaps scatter_ent tail; disjoint rows).
    gemm_nt<64, 4, true, false, false><<<dim3(gx, D / 64), 256>>>(
        p_rj, obj_W, obj_b, p_obj, R, ND, K_);
    scatter_obj<<<1184, 256>>>(rel_ids, tail_ids, state, out, E);
}

// round 7
// speedup vs baseline: 1.6356x; 1.2724x over previous
#include <cuda_runtime.h>
#include <math.h>

#define D    256
#define G3   768
#define MAXR 4096
#define NBK  444     // total blocks = 148 SMs * 3 (all wave-1 resident)
#define NCB  96      // compute blocks (barrier participants)
#define CH   8       // edges per cursor grab

// ---------------- device scratch (static globals; no allocation) ----------------
__device__ float g_sub[D];
__device__ float g_gi0[G3];
__device__ float g_gh0[G3];
__device__ float g_gi[G3];
__device__ float g_gh[(size_t)MAXR * G3];
__device__ float g_rj[(size_t)MAXR * D];
__device__ float g_obj[(size_t)MAXR * D];
__device__ unsigned g_bcnt;     // 96-block barrier counter (self-resetting)
__device__ unsigned g_bgen;     // barrier generation (monotonic across replays)
__device__ unsigned g_cdone;    // obj-table completion count (target 64)
__device__ unsigned g_cur_ent;  // ent-edge work cursor
__device__ unsigned g_cur_obj;  // obj-edge work cursor
__device__ unsigned g_ack;      // end-of-kernel reset ack (target NBK)

// ---------------- helpers -------------------------------------------------------
__device__ __forceinline__ float dot8(float4 a0, float4 a1, float4 x0, float4 x1) {
    return a0.x*x0.x + a0.y*x0.y + a0.z*x0.z + a0.w*x0.w
         + a1.x*x1.x + a1.y*x1.y + a1.z*x1.z + a1.w*x1.w;
}
__device__ __forceinline__ float wred(float v) {
#pragma unroll
    for (int o = 16; o; o >>= 1) v += __shfl_xor_sync(0xffffffffu, v, o);
    return v;
}
__device__ __forceinline__ float sigf(float x) { return 1.f / (1.f + __expf(-x)); }

__device__ __forceinline__ unsigned long long pack2(float x, float y) {
    unsigned long long r;
    asm("mov.b64 %0, {%1, %2};" : "=l"(r) : "f"(x), "f"(y));
    return r;
}
__device__ __forceinline__ void unpack2(unsigned long long v, float& x, float& y) {
    asm("mov.b64 {%0, %1}, %2;" : "=f"(x), "=f"(y) : "l"(v));
}
__device__ __forceinline__ void ffma2(unsigned long long& d, unsigned long long a,
                                      unsigned long long b) {
    asm("fma.rn.f32x2 %0, %1, %2, %0;" : "+l"(d) : "l"(a), "l"(b));
}

// barrier among the NCB compute blocks (all guaranteed wave-1 resident)
__device__ __forceinline__ void bar96() {
    __syncthreads();
    if (threadIdx.x == 0) {
        __threadfence();
        unsigned my = *(volatile unsigned*)&g_bgen;
        if (atomicAdd(&g_bcnt, 1u) == (unsigned)(NCB - 1)) {
            *(volatile unsigned*)&g_bcnt = 0;
            __threadfence();
            atomicAdd(&g_bgen, 1u);
        } else {
            while (*(volatile unsigned*)&g_bgen == my) { }
            __threadfence();
        }
    }
    __syncthreads();
}

// ---------------- in-kernel NT GEMM tile (f32x2 packed FMA) ---------------------
template <int BN, int TN, bool TANH>
__device__ void tile_gemm(const float* __restrict__ A, const float* __restrict__ B,
                          const float* __restrict__ bias, float* __restrict__ C,
                          int M, int ldc, int K, int m0, int n0,
                          float (*As)[68], float (*Bs)[132]) {
    const int BM = 64, BK = 32, TM = 4;
    int tid = threadIdx.x;
    unsigned long long acc[TM][TN / 2];
#pragma unroll
    for (int i = 0; i < TM; i++)
#pragma unroll
        for (int j = 0; j < TN / 2; j++) acc[i][j] = 0ull;
    int tm = (tid & 15) * TM;
    int tn = (tid >> 4) * TN;

    for (int k0 = 0; k0 < K; k0 += BK) {
#pragma unroll
        for (int i = 0; i < (BM * BK) / (256 * 4); i++) {
            int idx = tid + i * 256;
            int row = idx >> 3, c4 = idx & 7;
            float4 v = make_float4(0.f, 0.f, 0.f, 0.f);
            if (m0 + row < M) v = *(const float4*)&A[(size_t)(m0 + row) * K + k0 + c4 * 4];
            As[c4 * 4 + 0][row] = v.x; As[c4 * 4 + 1][row] = v.y;
            As[c4 * 4 + 2][row] = v.z; As[c4 * 4 + 3][row] = v.w;
        }
#pragma unroll
        for (int i = 0; i < (BN * BK) / (256 * 4); i++) {
            int idx = tid + i * 256;
            int row = idx >> 3, c4 = idx & 7;
            float4 v = *(const float4*)&B[(size_t)(n0 + row) * K + k0 + c4 * 4];
            Bs[c4 * 4 + 0][row] = v.x; Bs[c4 * 4 + 1][row] = v.y;
            Bs[c4 * 4 + 2][row] = v.z; Bs[c4 * 4 + 3][row] = v.w;
        }
        __syncthreads();
#pragma unroll
        for (int k = 0; k < BK; k++) {
            float4 av = *(const float4*)&As[k][tm];
            unsigned long long pa[TM];
            pa[0] = pack2(av.x, av.x); pa[1] = pack2(av.y, av.y);
            pa[2] = pack2(av.z, av.z); pa[3] = pack2(av.w, av.w);
            unsigned long long pb[TN / 2];
#pragma unroll
            for (int j4 = 0; j4 < TN / 4; j4++) {
                float4 bv = *(const float4*)&Bs[k][tn + j4 * 4];
                pb[j4 * 2 + 0] = pack2(bv.x, bv.y);
                pb[j4 * 2 + 1] = pack2(bv.z, bv.w);
            }
#pragma unroll
            for (int i = 0; i < TM; i++)
#pragma unroll
                for (int j = 0; j < TN / 2; j++) ffma2(acc[i][j], pa[i], pb[j]);
        }
        __syncthreads();
    }
#pragma unroll
    for (int i = 0; i < TM; i++) {
        int m = m0 + tm + i;
        if (m < M) {
#pragma unroll
            for (int j = 0; j < TN / 2; j++) {
                float vx, vy; unpack2(acc[i][j], vx, vy);
                int n = n0 + tn + j * 2;
                if (bias) { vx += bias[n]; vy += bias[n + 1]; }
                if (TANH) { vx = tanhf(vx); vy = tanhf(vy); }
                C[(size_t)m * ldc + n]     = vx;
                C[(size_t)m * ldc + n + 1] = vy;
            }
        }
    }
}

// ---------------- the ONE kernel ------------------------------------------------
__global__ void __launch_bounds__(256, 3)
fused_kernel(const float* __restrict__ sub_W, const float* __restrict__ W_ih,
             const float* __restrict__ W_hh,  const float* __restrict__ mask,
             const float* __restrict__ enc,   const float* __restrict__ sub_b,
             const float* __restrict__ b_ih,  const float* __restrict__ b_hh,
             const float* __restrict__ relT,  const float* __restrict__ obj_W,
             const float* __restrict__ obj_b, const float* __restrict__ entT,
             const int* __restrict__ rel_ids, const int* __restrict__ tail_ids,
             const int* __restrict__ st,      const int* __restrict__ org,
             const int* __restrict__ seed_p,  float* __restrict__ out,
             int R, int E) {
    __shared__ float sAs[32][68];
    __shared__ float sBs[32][132];
    int t = threadIdx.x, w = t >> 5, l = t & 31, b = blockIdx.x;

    if (b < NCB) {
        // ===================== compute phases (96 blocks) =====================
        // p0: sub = tanh(sub_W@mask+sub_b) (+ seed row) ; gi0 = W_ih@enc+b_ih
#pragma unroll
        for (int it = 0; it < 2; it++) {
            int j = it * (NCB * 8) + b * 8 + w;
            if (j < 1024) {
                const float4 *Wr, *x; float bias;
                if (j < 256) { Wr = (const float4*)(sub_W + (size_t)j * D); x = (const float4*)mask; bias = sub_b[j]; }
                else { Wr = (const float4*)(W_ih + (size_t)(j - 256) * D); x = (const float4*)enc; bias = b_ih[j - 256]; }
                float acc = wred(dot8(Wr[l], Wr[l + 32], __ldg(x + l), __ldg(x + l + 32)));
                if (l == 0) {
                    acc += bias;
                    if (j < 256) { float tt = tanhf(acc); g_sub[j] = tt; out[(size_t)seed_p[0] * D + j] = tt; }
                    else g_gi0[j - 256] = acc;
                }
            }
        }
        bar96();
        // p1: gh0 = W_hh @ sub + b_hh
        {
            int j = b * 8 + w;
            const float4* Wr = (const float4*)(W_hh + (size_t)j * D);
            const float4* x  = (const float4*)g_sub;
            float acc = wred(dot8(Wr[l], Wr[l + 32], x[l], x[l + 32]));
            if (l == 0) g_gh0[j] = acc + b_hh[j];
        }
        bar96();
        // p2: r0 (per-block smem) ; gi = W_ih @ r0 + b_ih
        {
            float* r0s = &sBs[0][0];
            float r = sigf(g_gi0[t] + g_gh0[t]);
            float z = sigf(g_gi0[D + t] + g_gh0[D + t]);
            float n = tanhf(g_gi0[2 * D + t] + r * g_gh0[2 * D + t]);
            r0s[t] = (1.f - z) * n + z * g_sub[t];
            __syncthreads();
            int j = b * 8 + w;
            const float4* Wr = (const float4*)(W_ih + (size_t)j * D);
            const float4* x  = (const float4*)r0s;
            float acc = wred(dot8(Wr[l], Wr[l + 32], x[l], x[l + 32]));
            if (l == 0) g_gi[j] = acc + b_ih[j];
        }
        bar96();
        // p3: gh = relT @ W_hh^T  (96 tiles of 64x128 over [R, 768])
        tile_gemm<128, 8, false>(relT, W_hh, nullptr, g_gh, R, G3, D,
                                 (b % 16) * 64, (b / 16) * 128, sAs, sBs);
        bar96();
        // p4: rj per relation
        {
            float gi_r = g_gi[t], gi_z = g_gi[D + t], gi_n = g_gi[2 * D + t];
            float bh_r = b_hh[t], bh_z = b_hh[D + t], bh_n = b_hh[2 * D + t];
            for (int r = b; r < R; r += NCB) {
                const float* gh = g_gh + (size_t)r * G3;
                float rr = sigf(gi_r + gh[t] + bh_r);
                float z  = sigf(gi_z + gh[D + t] + bh_z);
                float n  = tanhf(gi_n + rr * (gh[2 * D + t] + bh_n));
                g_rj[(size_t)r * D + t] = (1.f - z) * n + z * relT[(size_t)r * D + t];
            }
        }
        bar96();
        // p5: obj = tanh(rj @ obj_W^T + obj_b) on blocks 0..63; each signals done.
        if (b < 64) {
            tile_gemm<64, 4, true>(g_rj, obj_W, obj_b, g_obj, R, D, D,
                                   (b % 16) * 64, (b / 16) * 64, sAs, sBs);
            __syncthreads();
            if (t == 0) { __threadfence(); atomicAdd(&g_cdone, 1u); }
        }
        // fall through: compute blocks help with ent scatter, then obj scatter
    }

    // ===================== ent scatter (dynamic cursor) =====================
    for (;;) {
        unsigned base;
        if (l == 0) base = atomicAdd(&g_cur_ent, (unsigned)CH);
        base = __shfl_sync(0xffffffffu, base, 0);
        if (base >= (unsigned)E) break;
        unsigned end = base + CH; if (end > (unsigned)E) end = E;
        for (unsigned e = base; e < end; e++) {
            if (st[e] == 1) {
                const float4* s = (const float4*)(entT + (size_t)org[e] * D);
                float4* d = (float4*)(out + (size_t)tail_ids[e] * D);
                float4 v0 = __ldcs(s + l), v1 = __ldcs(s + l + 32);
                __stcs(d + l, v0); __stcs(d + l + 32, v1);
            }
        }
    }

    // ===================== wait for obj table, then obj scatter =============
    if (t == 0) { while (*(volatile unsigned*)&g_cdone < 64u) { } }
    __syncthreads();
    __threadfence();
    for (;;) {
        unsigned base;
        if (l == 0) base = atomicAdd(&g_cur_obj, (unsigned)CH);
        base = __shfl_sync(0xffffffffu, base, 0);
        if (base >= (unsigned)E) break;
        unsigned end = base + CH; if (end > (unsigned)E) end = E;
        for (unsigned e = base; e < end; e++) {
            if (st[e] != 1) {
                const float4* s = (const float4*)(g_obj + (size_t)rel_ids[e] * D);
                float4* d = (float4*)(out + (size_t)tail_ids[e] * D);
                float4 v0 = __ldg(s + l), v1 = __ldg(s + l + 32);
                __stcs(d + l, v0); __stcs(d + l + 32, v1);
            }
        }
    }

    // ===================== reset shared state for next graph replay =========
    __syncthreads();
    if (t == 0) {
        if (atomicAdd(&g_ack, 1u) == (unsigned)(NBK - 1)) {
            g_cdone = 0u; g_cur_ent = 0u; g_cur_obj = 0u;
            __threadfence();
            *(volatile unsigned*)&g_ack = 0u;
        }
    }
}

// --------------------------------- launcher -------------------------------------
extern "C" void kernel_launch(void* const* d_in, const int* in_sizes, int n_in,
                              void* d_out, int out_size) {
    const float* encoder = (const float*)d_in[0];
    const float* mask    = (const float*)d_in[1];
    const float* entT    = (const float*)d_in[2];
    const float* relT    = (const float*)d_in[3];
    const float* W_ih    = (const float*)d_in[4];
    const float* W_hh    = (const float*)d_in[5];
    const float* b_ih    = (const float*)d_in[6];
    const float* b_hh    = (const float*)d_in[7];
    const float* sub_W   = (const float*)d_in[8];
    const float* sub_b   = (const float*)d_in[9];
    const float* obj_W   = (const float*)d_in[10];
    const float* obj_b   = (const float*)d_in[11];
    const int*   rel_ids = (const int*)d_in[12];
    const int*   tail_ids= (const int*)d_in[13];
    const int*   state   = (const int*)d_in[14];
    const int*   origin  = (const int*)d_in[15];
    const int*   seed_p  = (const int*)d_in[16];
    float* out = (float*)d_out;

    int E = in_sizes[12];
    int R = in_sizes[3] / D;
    if (R > MAXR) R = MAXR;

    fused_kernel<<<NBK, 256>>>(sub_W, W_ih, W_hh, mask, encoder, sub_b, b_ih, b_hh,
                               relT, obj_W, obj_b, entT,
                               rel_ids, tail_ids, state, origin, seed_p, out, R, E);
}